// round 9
// baseline (speedup 1.0000x reference)
#include <cuda_runtime.h>
#include <math.h>
#include <stdint.h>

// Problem constants
#define B_   64
#define IN_  512
#define M_   1024
#define NG   6          // q,k,v,i,f,o  (pre-activation order in g_pre)
#define NSPLIT 8
#define KSL  (IN_ / NSPLIT)   // 64

// pre-activation accumulator: [b][gate*M_ + m], accumulated via atomicAdd
__device__ float g_pre[B_ * NG * M_];

__device__ __forceinline__ float sigmoidf_(float v) {
    return 1.f / (1.f + __expf(-v));
}

// ---------------------------------------------------------------------------
// TF32 helpers
// ---------------------------------------------------------------------------
__device__ __forceinline__ uint32_t f2tf32(float f) {
    uint32_t u;
    asm("cvt.rna.tf32.f32 %0, %1;" : "=r"(u) : "f"(f));
    return u;
}

__device__ __forceinline__ void mma_tf32(float* c, const uint32_t* a, const uint32_t* b) {
    asm("mma.sync.aligned.m16n8k8.row.col.f32.tf32.tf32.f32 "
        "{%0,%1,%2,%3},{%4,%5,%6,%7},{%8,%9},{%0,%1,%2,%3};"
        : "+f"(c[0]), "+f"(c[1]), "+f"(c[2]), "+f"(c[3])
        : "r"(a[0]), "r"(a[1]), "r"(a[2]), "r"(a[3]),
          "r"(b[0]), "r"(b[1]));
}

// ---------------------------------------------------------------------------
// Kernel 0: zero the pre-activation accumulator (re-run every launch).
// 384 blocks x 256 threads x 1 float4 = 393216 floats.
// ---------------------------------------------------------------------------
__global__ __launch_bounds__(256)
void zero_pre()
{
    const int i = blockIdx.x * 256 + threadIdx.x;
    ((float4*)g_pre)[i] = make_float4(0.f, 0.f, 0.f, 0.f);
}

// ---------------------------------------------------------------------------
// Kernel 1: split-K TF32 tensor-core GEMM, atomic accumulation.
// grid = (96, 8): bx -> 64-wide column tile over 6144 gate-cols,
//                 by -> K slice (64 wide). Block tile 64x64x32 double-buffered.
// Epilogue: atomicAdd (REDG.F32) raw partials into g_pre — no reduce kernel.
// ---------------------------------------------------------------------------
__global__ __launch_bounds__(256)
void gates_mma_sk(const float* __restrict__ x,
                  const float* __restrict__ Wq, const float* __restrict__ Wk,
                  const float* __restrict__ Wv, const float* __restrict__ Wi,
                  const float* __restrict__ Wf, const float* __restrict__ Wo)
{
    const int n_global0 = blockIdx.x * 64;          // [0, 6144)
    const int gate      = n_global0 >> 10;
    const int n_local0  = n_global0 & (M_ - 1);
    const int s         = blockIdx.y;
    const int k_base    = s * KSL;

    const float* W;
    switch (gate) {
        case 0: W = Wq; break;
        case 1: W = Wk; break;
        case 2: W = Wv; break;
        case 3: W = Wi; break;
        case 4: W = Wf; break;
        default: W = Wo; break;
    }

    __shared__ uint32_t Xs[2][64][36];   // [buf][b][k] tf32 bits
    __shared__ uint32_t Ws[2][64][36];   // [buf][n][k] tf32 bits

    const int tid  = threadIdx.x;
    const int wid  = tid >> 5;
    const int lane = tid & 31;
    const int g    = lane >> 2;        // groupID 0..7
    const int tig  = lane & 3;         // thread-in-group 0..3
    const int warp_m = wid & 1;        // 32 rows each
    const int warp_n = wid >> 1;       // 16 cols each

    const int lrow0 = tid >> 3;          // 0..31
    const int lrow1 = lrow0 + 32;
    const int lcol  = (tid & 7) * 4;

    const float* xg0 = x + lrow0 * IN_ + k_base + lcol;
    const float* xg1 = x + lrow1 * IN_ + k_base + lcol;
    const float* wg0 = W + (n_local0 + lrow0) * IN_ + k_base + lcol;
    const float* wg1 = W + (n_local0 + lrow1) * IN_ + k_base + lcol;

    float acc[2][2][4];
    #pragma unroll
    for (int mt = 0; mt < 2; mt++)
        #pragma unroll
        for (int nt = 0; nt < 2; nt++)
            #pragma unroll
            for (int e = 0; e < 4; e++) acc[mt][nt][e] = 0.f;

    float4 xr0, xr1, wr0, wr1;
    xr0 = *(const float4*)xg0;
    xr1 = *(const float4*)xg1;
    wr0 = *(const float4*)wg0;
    wr1 = *(const float4*)wg1;

    {
        uint4 u;
        u.x = f2tf32(xr0.x); u.y = f2tf32(xr0.y); u.z = f2tf32(xr0.z); u.w = f2tf32(xr0.w);
        *(uint4*)&Xs[0][lrow0][lcol] = u;
        u.x = f2tf32(xr1.x); u.y = f2tf32(xr1.y); u.z = f2tf32(xr1.z); u.w = f2tf32(xr1.w);
        *(uint4*)&Xs[0][lrow1][lcol] = u;
        u.x = f2tf32(wr0.x); u.y = f2tf32(wr0.y); u.z = f2tf32(wr0.z); u.w = f2tf32(wr0.w);
        *(uint4*)&Ws[0][lrow0][lcol] = u;
        u.x = f2tf32(wr1.x); u.y = f2tf32(wr1.y); u.z = f2tf32(wr1.z); u.w = f2tf32(wr1.w);
        *(uint4*)&Ws[0][lrow1][lcol] = u;
    }
    __syncthreads();

    int buf = 0;
    #pragma unroll 1
    for (int it = 0; it < KSL / 32; it++) {
        if (it < KSL / 32 - 1) {
            const int k0 = (it + 1) * 32;
            xr0 = *(const float4*)(xg0 + k0);
            xr1 = *(const float4*)(xg1 + k0);
            wr0 = *(const float4*)(wg0 + k0);
            wr1 = *(const float4*)(wg1 + k0);
        }

        #pragma unroll
        for (int ks = 0; ks < 4; ks++) {
            const int ko = ks * 8;
            uint32_t af[2][4];
            #pragma unroll
            for (int mt = 0; mt < 2; mt++) {
                const int r = warp_m * 32 + mt * 16 + g;
                af[mt][0] = Xs[buf][r][ko + tig];
                af[mt][1] = Xs[buf][r + 8][ko + tig];
                af[mt][2] = Xs[buf][r][ko + tig + 4];
                af[mt][3] = Xs[buf][r + 8][ko + tig + 4];
            }
            uint32_t bfr[2][2];
            #pragma unroll
            for (int nt = 0; nt < 2; nt++) {
                const int c = warp_n * 16 + nt * 8 + g;
                bfr[nt][0] = Ws[buf][c][ko + tig];
                bfr[nt][1] = Ws[buf][c][ko + tig + 4];
            }
            #pragma unroll
            for (int mt = 0; mt < 2; mt++)
                #pragma unroll
                for (int nt = 0; nt < 2; nt++)
                    mma_tf32(acc[mt][nt], af[mt], bfr[nt]);
        }

        if (it < KSL / 32 - 1) {
            const int nb = buf ^ 1;
            uint4 u;
            u.x = f2tf32(xr0.x); u.y = f2tf32(xr0.y); u.z = f2tf32(xr0.z); u.w = f2tf32(xr0.w);
            *(uint4*)&Xs[nb][lrow0][lcol] = u;
            u.x = f2tf32(xr1.x); u.y = f2tf32(xr1.y); u.z = f2tf32(xr1.z); u.w = f2tf32(xr1.w);
            *(uint4*)&Xs[nb][lrow1][lcol] = u;
            u.x = f2tf32(wr0.x); u.y = f2tf32(wr0.y); u.z = f2tf32(wr0.z); u.w = f2tf32(wr0.w);
            *(uint4*)&Ws[nb][lrow0][lcol] = u;
            u.x = f2tf32(wr1.x); u.y = f2tf32(wr1.y); u.z = f2tf32(wr1.z); u.w = f2tf32(wr1.w);
            *(uint4*)&Ws[nb][lrow1][lcol] = u;
            __syncthreads();
            buf = nb;
        }
    }

    // epilogue: atomic accumulation of raw partials into g_pre[b][n_global]
    #pragma unroll
    for (int mt = 0; mt < 2; mt++) {
        const int r0 = warp_m * 32 + mt * 16 + g;   // batch row
        #pragma unroll
        for (int nt = 0; nt < 2; nt++) {
            const int ncol = n_global0 + warp_n * 16 + nt * 8 + 2 * tig;
            atomicAdd(&g_pre[(size_t)r0 * (NG * M_) + ncol],       acc[mt][nt][0]);
            atomicAdd(&g_pre[(size_t)r0 * (NG * M_) + ncol + 1],   acc[mt][nt][1]);
            atomicAdd(&g_pre[(size_t)(r0 + 8) * (NG * M_) + ncol],     acc[mt][nt][2]);
            atomicAdd(&g_pre[(size_t)(r0 + 8) * (NG * M_) + ncol + 1], acc[mt][nt][3]);
        }
    }
}

// ---------------------------------------------------------------------------
// Kernel 2 (fused): bias+activation + C_t update + h_tilde + n_t + denom + h_t.
// grid = (16, 64): blockIdx.y = batch, blockIdx.x = 64-row chunk.
// Prologue: activate q,k,i,f from g_pre (+bias), build n_t (+write on bx==0),
// block-reduce denom. Main loop: streaming C update (MLP=8), warp-reduced dot
// with q, lane0 applies o-sigmoid and writes h_t.
// ---------------------------------------------------------------------------
__global__ __launch_bounds__(256, 3)
void update_C(const float* __restrict__ Cprev, const float* __restrict__ nprev,
              const float* __restrict__ bq, const float* __restrict__ bk,
              const float* __restrict__ bv, const float* __restrict__ bi,
              const float* __restrict__ bf, const float* __restrict__ bo,
              float* __restrict__ Cout, float* __restrict__ out_h,
              float* __restrict__ out_n)
{
    const int b = blockIdx.y;
    __shared__ float sk[M_];
    __shared__ float sq[M_];
    __shared__ float red[8];
    __shared__ float s_inv;

    const float* pre = g_pre + (size_t)b * (NG * M_);   // [gate*M_ + m]
    const int warp = threadIdx.x >> 5;
    const int lane = threadIdx.x & 31;

    // --- prologue: activate q,k,i,f; n_t; denom ---
    {
        const int t = threadIdx.x;    // float4 index over m (1024/4 = 256)
        float4 q4 = ((const float4*)(pre + 0 * M_))[t];
        float4 k4 = ((const float4*)(pre + 1 * M_))[t];
        float4 i4 = ((const float4*)(pre + 3 * M_))[t];
        float4 f4 = ((const float4*)(pre + 4 * M_))[t];
        const float4 bq4 = ((const float4*)bq)[t];
        const float4 bk4 = ((const float4*)bk)[t];
        const float4 bi4 = ((const float4*)bi)[t];
        const float4 bf4 = ((const float4*)bf)[t];

        q4.x += bq4.x; q4.y += bq4.y; q4.z += bq4.z; q4.w += bq4.w;
        k4.x = (k4.x + bk4.x) * 0.03125f;
        k4.y = (k4.y + bk4.y) * 0.03125f;
        k4.z = (k4.z + bk4.z) * 0.03125f;
        k4.w = (k4.w + bk4.w) * 0.03125f;
        i4.x = __expf(i4.x + bi4.x);
        i4.y = __expf(i4.y + bi4.y);
        i4.z = __expf(i4.z + bi4.z);
        i4.w = __expf(i4.w + bi4.w);
        f4.x = sigmoidf_(f4.x + bf4.x);
        f4.y = sigmoidf_(f4.y + bf4.y);
        f4.z = sigmoidf_(f4.z + bf4.z);
        f4.w = sigmoidf_(f4.w + bf4.w);

        ((float4*)sk)[t] = k4;
        ((float4*)sq)[t] = q4;

        float4 p4 = ((const float4*)(nprev + b * M_))[t];
        float4 n4;
        n4.x = fmaf(f4.x, p4.x, i4.x * k4.x);
        n4.y = fmaf(f4.y, p4.y, i4.y * k4.y);
        n4.z = fmaf(f4.z, p4.z, i4.z * k4.z);
        n4.w = fmaf(f4.w, p4.w, i4.w * k4.w);
        if (blockIdx.x == 0)
            ((float4*)(out_n + b * M_))[t] = n4;

        float part = n4.x * q4.x + n4.y * q4.y + n4.z * q4.z + n4.w * q4.w;
        #pragma unroll
        for (int off = 16; off; off >>= 1)
            part += __shfl_xor_sync(0xffffffffu, part, off);
        if (lane == 0) red[warp] = part;
        __syncthreads();
        if (threadIdx.x == 0) {
            float d = red[0] + red[1] + red[2] + red[3]
                    + red[4] + red[5] + red[6] + red[7];
            s_inv = 1.0f / fmaxf(d, 1.0f);
        }
        __syncthreads();
    }
    const float inv = s_inv;

    const float4* sk4 = (const float4*)sk;
    const float4* sq4 = (const float4*)sq;

    #pragma unroll
    for (int r = 0; r < 8; r++) {
        const int m = blockIdx.x * 64 + r * 8 + warp;
        const float fm = sigmoidf_(pre[4 * M_ + m] + bf[m]);
        const float cm = __expf(pre[3 * M_ + m] + bi[m]) * (pre[2 * M_ + m] + bv[m]);

        const float4* cp = (const float4*)(Cprev + ((size_t)b * M_ + m) * M_);
        float4*       co = (float4*)(Cout  + ((size_t)b * M_ + m) * M_);

        // issue the whole row's loads first: MLP = 8
        float4 c[8];
        #pragma unroll
        for (int j = 0; j < 8; j++)
            c[j] = __ldcs(cp + j * 32 + lane);

        float dot0 = 0.f, dot1 = 0.f;
        #pragma unroll
        for (int j = 0; j < 8; j++) {
            const int n4 = j * 32 + lane;
            float4 kk = sk4[n4];
            float4 qq = sq4[n4];
            float4 o;
            o.x = fmaf(fm, c[j].x, cm * kk.x);
            o.y = fmaf(fm, c[j].y, cm * kk.y);
            o.z = fmaf(fm, c[j].z, cm * kk.z);
            o.w = fmaf(fm, c[j].w, cm * kk.w);
            __stcs(co + n4, o);
            if (j & 1) {
                dot1 = fmaf(o.x, qq.x, dot1);
                dot1 = fmaf(o.y, qq.y, dot1);
                dot1 = fmaf(o.z, qq.z, dot1);
                dot1 = fmaf(o.w, qq.w, dot1);
            } else {
                dot0 = fmaf(o.x, qq.x, dot0);
                dot0 = fmaf(o.y, qq.y, dot0);
                dot0 = fmaf(o.z, qq.z, dot0);
                dot0 = fmaf(o.w, qq.w, dot0);
            }
        }
        float dot = dot0 + dot1;
        #pragma unroll
        for (int off = 16; off; off >>= 1)
            dot += __shfl_xor_sync(0xffffffffu, dot, off);
        if (lane == 0) {
            const float om = sigmoidf_(pre[5 * M_ + m] + bo[m]);
            out_h[b * M_ + m] = om * dot * inv;
        }
    }
}

// ---------------------------------------------------------------------------
// Launch. Inputs (metadata order):
// 0 x, 1 h_prev, 2 c_prev, 3 C_prev, 4 n_prev, 5 m_prev,
// 6 Wq, 7 bq, 8 Wk, 9 bk, 10 Wv, 11 bv, 12 Wi, 13 bi, 14 Wf, 15 bf, 16 Wo, 17 bo
// Output: concat(h_t [64*1024], C_t [64*1024*1024], n_t [64*1024])
// ---------------------------------------------------------------------------
extern "C" void kernel_launch(void* const* d_in, const int* in_sizes, int n_in,
                              void* d_out, int out_size)
{
    const float* x     = (const float*)d_in[0];
    const float* Cprev = (const float*)d_in[3];
    const float* nprev = (const float*)d_in[4];

    const float* Wq = (const float*)d_in[6];  const float* bq = (const float*)d_in[7];
    const float* Wk = (const float*)d_in[8];  const float* bk = (const float*)d_in[9];
    const float* Wv = (const float*)d_in[10]; const float* bv = (const float*)d_in[11];
    const float* Wi = (const float*)d_in[12]; const float* bi = (const float*)d_in[13];
    const float* Wf = (const float*)d_in[14]; const float* bf = (const float*)d_in[15];
    const float* Wo = (const float*)d_in[16]; const float* bo = (const float*)d_in[17];

    float* out   = (float*)d_out;
    float* out_h = out;                                    // [64*1024]
    float* out_C = out + (size_t)B_ * M_;                  // [64*1024*1024]
    float* out_n = out + (size_t)B_ * M_ + (size_t)B_ * M_ * M_;

    zero_pre<<<384, 256>>>();

    dim3 grid1(96, NSPLIT);
    gates_mma_sk<<<grid1, 256>>>(x, Wq, Wk, Wv, Wi, Wf, Wo);

    dim3 grid2(16, 64);
    update_C<<<grid2, 256>>>(Cprev, nprev, bq, bk, bv, bi, bf, bo,
                             out_C, out_h, out_n);
}

// round 10
// speedup vs baseline: 1.0607x; 1.0607x over previous
#include <cuda_runtime.h>
#include <math.h>
#include <stdint.h>

// Problem constants
#define B_   64
#define IN_  512
#define M_   1024
#define NG   6          // q,k,v,i,f,o
#define NSPLIT 4
#define KSL  (IN_ / NSPLIT)   // 128

// scratch
__device__ float g_gates[NG * B_ * M_];          // [gate][b][m]
__device__ float g_part[NSPLIT * B_ * NG * M_];  // [s][b][n_global]

// ---------------------------------------------------------------------------
// TF32 helpers
// ---------------------------------------------------------------------------
__device__ __forceinline__ uint32_t f2tf32(float f) {
    uint32_t u;
    asm("cvt.rna.tf32.f32 %0, %1;" : "=r"(u) : "f"(f));
    return u;
}

__device__ __forceinline__ void mma_tf32(float* c, const uint32_t* a, const uint32_t* b) {
    asm("mma.sync.aligned.m16n8k8.row.col.f32.tf32.tf32.f32 "
        "{%0,%1,%2,%3},{%4,%5,%6,%7},{%8,%9},{%0,%1,%2,%3};"
        : "+f"(c[0]), "+f"(c[1]), "+f"(c[2]), "+f"(c[3])
        : "r"(a[0]), "r"(a[1]), "r"(a[2]), "r"(a[3]),
          "r"(b[0]), "r"(b[1]));
}

// ---------------------------------------------------------------------------
// Kernel 1a: split-K TF32 tensor-core GEMM partials. (R8 version, measured 10.4us)
// grid = (96, 4). Block tile 64x64x32 double-buffered, warp grid 2m x 4n.
// ---------------------------------------------------------------------------
__global__ __launch_bounds__(256)
void gates_mma_sk(const float* __restrict__ x,
                  const float* __restrict__ Wq, const float* __restrict__ Wk,
                  const float* __restrict__ Wv, const float* __restrict__ Wi,
                  const float* __restrict__ Wf, const float* __restrict__ Wo)
{
    const int n_global0 = blockIdx.x * 64;          // [0, 6144)
    const int gate      = n_global0 >> 10;
    const int n_local0  = n_global0 & (M_ - 1);
    const int s         = blockIdx.y;
    const int k_base    = s * KSL;

    const float* W;
    switch (gate) {
        case 0: W = Wq; break;
        case 1: W = Wk; break;
        case 2: W = Wv; break;
        case 3: W = Wi; break;
        case 4: W = Wf; break;
        default: W = Wo; break;
    }

    __shared__ uint32_t Xs[2][64][36];   // [buf][b][k] tf32 bits
    __shared__ uint32_t Ws[2][64][36];   // [buf][n][k] tf32 bits

    const int tid  = threadIdx.x;
    const int wid  = tid >> 5;
    const int lane = tid & 31;
    const int g    = lane >> 2;
    const int tig  = lane & 3;
    const int warp_m = wid & 1;
    const int warp_n = wid >> 1;

    const int lrow0 = tid >> 3;
    const int lrow1 = lrow0 + 32;
    const int lcol  = (tid & 7) * 4;

    const float* xg0 = x + lrow0 * IN_ + k_base + lcol;
    const float* xg1 = x + lrow1 * IN_ + k_base + lcol;
    const float* wg0 = W + (n_local0 + lrow0) * IN_ + k_base + lcol;
    const float* wg1 = W + (n_local0 + lrow1) * IN_ + k_base + lcol;

    float acc[2][2][4];
    #pragma unroll
    for (int mt = 0; mt < 2; mt++)
        #pragma unroll
        for (int nt = 0; nt < 2; nt++)
            #pragma unroll
            for (int e = 0; e < 4; e++) acc[mt][nt][e] = 0.f;

    float4 xr0, xr1, wr0, wr1;
    xr0 = *(const float4*)xg0;
    xr1 = *(const float4*)xg1;
    wr0 = *(const float4*)wg0;
    wr1 = *(const float4*)wg1;

    {
        uint4 u;
        u.x = f2tf32(xr0.x); u.y = f2tf32(xr0.y); u.z = f2tf32(xr0.z); u.w = f2tf32(xr0.w);
        *(uint4*)&Xs[0][lrow0][lcol] = u;
        u.x = f2tf32(xr1.x); u.y = f2tf32(xr1.y); u.z = f2tf32(xr1.z); u.w = f2tf32(xr1.w);
        *(uint4*)&Xs[0][lrow1][lcol] = u;
        u.x = f2tf32(wr0.x); u.y = f2tf32(wr0.y); u.z = f2tf32(wr0.z); u.w = f2tf32(wr0.w);
        *(uint4*)&Ws[0][lrow0][lcol] = u;
        u.x = f2tf32(wr1.x); u.y = f2tf32(wr1.y); u.z = f2tf32(wr1.z); u.w = f2tf32(wr1.w);
        *(uint4*)&Ws[0][lrow1][lcol] = u;
    }
    __syncthreads();

    int buf = 0;
    #pragma unroll 1
    for (int it = 0; it < KSL / 32; it++) {
        if (it < KSL / 32 - 1) {
            const int k0 = (it + 1) * 32;
            xr0 = *(const float4*)(xg0 + k0);
            xr1 = *(const float4*)(xg1 + k0);
            wr0 = *(const float4*)(wg0 + k0);
            wr1 = *(const float4*)(wg1 + k0);
        }

        #pragma unroll
        for (int ks = 0; ks < 4; ks++) {
            const int ko = ks * 8;
            uint32_t af[2][4];
            #pragma unroll
            for (int mt = 0; mt < 2; mt++) {
                const int r = warp_m * 32 + mt * 16 + g;
                af[mt][0] = Xs[buf][r][ko + tig];
                af[mt][1] = Xs[buf][r + 8][ko + tig];
                af[mt][2] = Xs[buf][r][ko + tig + 4];
                af[mt][3] = Xs[buf][r + 8][ko + tig + 4];
            }
            uint32_t bfr[2][2];
            #pragma unroll
            for (int nt = 0; nt < 2; nt++) {
                const int c = warp_n * 16 + nt * 8 + g;
                bfr[nt][0] = Ws[buf][c][ko + tig];
                bfr[nt][1] = Ws[buf][c][ko + tig + 4];
            }
            #pragma unroll
            for (int mt = 0; mt < 2; mt++)
                #pragma unroll
                for (int nt = 0; nt < 2; nt++)
                    mma_tf32(acc[mt][nt], af[mt], bfr[nt]);
        }

        if (it < KSL / 32 - 1) {
            const int nb = buf ^ 1;
            uint4 u;
            u.x = f2tf32(xr0.x); u.y = f2tf32(xr0.y); u.z = f2tf32(xr0.z); u.w = f2tf32(xr0.w);
            *(uint4*)&Xs[nb][lrow0][lcol] = u;
            u.x = f2tf32(xr1.x); u.y = f2tf32(xr1.y); u.z = f2tf32(xr1.z); u.w = f2tf32(xr1.w);
            *(uint4*)&Xs[nb][lrow1][lcol] = u;
            u.x = f2tf32(wr0.x); u.y = f2tf32(wr0.y); u.z = f2tf32(wr0.z); u.w = f2tf32(wr0.w);
            *(uint4*)&Ws[nb][lrow0][lcol] = u;
            u.x = f2tf32(wr1.x); u.y = f2tf32(wr1.y); u.z = f2tf32(wr1.z); u.w = f2tf32(wr1.w);
            *(uint4*)&Ws[nb][lrow1][lcol] = u;
            __syncthreads();
            buf = nb;
        }
    }

    // write raw partials (L2-resident)
    float* outp = g_part + (size_t)s * (B_ * NG * M_);
    #pragma unroll
    for (int mt = 0; mt < 2; mt++) {
        const int r0 = warp_m * 32 + mt * 16 + g;
        #pragma unroll
        for (int nt = 0; nt < 2; nt++) {
            const int ncol = n_global0 + warp_n * 16 + nt * 8 + 2 * tig;
            *(float2*)&outp[(size_t)r0 * (NG * M_) + ncol] =
                make_float2(acc[mt][nt][0], acc[mt][nt][1]);
            *(float2*)&outp[(size_t)(r0 + 8) * (NG * M_) + ncol] =
                make_float2(acc[mt][nt][2], acc[mt][nt][3]);
        }
    }
}

// ---------------------------------------------------------------------------
// Kernel 1b: reduce partials + bias + activation -> g_gates[gate][b][m]
// ---------------------------------------------------------------------------
__global__ __launch_bounds__(256)
void gates_reduce(const float* __restrict__ bq, const float* __restrict__ bk,
                  const float* __restrict__ bv, const float* __restrict__ bi,
                  const float* __restrict__ bf, const float* __restrict__ bo)
{
    const int idx = blockIdx.x * 256 + threadIdx.x;   // [0, 98304)
    const int b   = idx / (NG * M_ / 4);
    const int c4  = idx % (NG * M_ / 4);
    const int n   = c4 * 4;
    const int gate = n >> 10;
    const int nl   = n & (M_ - 1);

    const float* bias;
    switch (gate) {
        case 0: bias = bq; break;
        case 1: bias = bk; break;
        case 2: bias = bv; break;
        case 3: bias = bi; break;
        case 4: bias = bf; break;
        default: bias = bo; break;
    }

    float4 acc = *(const float4*)&g_part[((size_t)0 * B_ + b) * (NG * M_) + n];
    #pragma unroll
    for (int s = 1; s < NSPLIT; s++) {
        float4 p = *(const float4*)&g_part[((size_t)s * B_ + b) * (NG * M_) + n];
        acc.x += p.x; acc.y += p.y; acc.z += p.z; acc.w += p.w;
    }
    const float4 bv4 = *(const float4*)&bias[nl];
    acc.x += bv4.x; acc.y += bv4.y; acc.z += bv4.z; acc.w += bv4.w;

    if (gate == 1) {
        acc.x *= 0.03125f; acc.y *= 0.03125f; acc.z *= 0.03125f; acc.w *= 0.03125f;
    } else if (gate == 3) {
        acc.x = __expf(acc.x); acc.y = __expf(acc.y);
        acc.z = __expf(acc.z); acc.w = __expf(acc.w);
    } else if (gate >= 4) {
        acc.x = 1.f / (1.f + __expf(-acc.x));
        acc.y = 1.f / (1.f + __expf(-acc.y));
        acc.z = 1.f / (1.f + __expf(-acc.z));
        acc.w = 1.f / (1.f + __expf(-acc.w));
    }
    *(float4*)&g_gates[(size_t)gate * (B_ * M_) + b * M_ + nl] = acc;
}

// ---------------------------------------------------------------------------
// Kernel 2 (fused, pipelined — R7 version, measured 82.2us):
// C_t update + h_tilde + n_t + denom + h_t.
// grid = (16, 64). Cross-row software pipeline: row r+1's 8 streaming loads
// are issued before row r's compute/store/reduce.
// ---------------------------------------------------------------------------
__global__ __launch_bounds__(256)
void update_C(const float* __restrict__ Cprev, const float* __restrict__ nprev,
              float* __restrict__ Cout, float* __restrict__ out_h,
              float* __restrict__ out_n)
{
    const int b = blockIdx.y;
    __shared__ float sk[M_];
    __shared__ float sq[M_];
    __shared__ float red[8];
    __shared__ float s_inv;

    const float* gq = g_gates + 0 * (B_ * M_) + b * M_;
    const float* gk = g_gates + 1 * (B_ * M_) + b * M_;
    ((float4*)sk)[threadIdx.x] = ((const float4*)gk)[threadIdx.x];
    ((float4*)sq)[threadIdx.x] = ((const float4*)gq)[threadIdx.x];

    const int warp = threadIdx.x >> 5;
    const int lane = threadIdx.x & 31;
    const float* gv = g_gates + 2 * (B_ * M_) + b * M_;
    const float* gi = g_gates + 3 * (B_ * M_) + b * M_;
    const float* gf = g_gates + 4 * (B_ * M_) + b * M_;
    const float* go = g_gates + 5 * (B_ * M_) + b * M_;

    __syncthreads();

    // --- denom prologue: n_t = f*n_prev + i*k ; part = n_t . q ---
    {
        const int t = threadIdx.x;
        float4 f4 = ((const float4*)gf)[t];
        float4 i4 = ((const float4*)gi)[t];
        float4 p4 = ((const float4*)(nprev + b * M_))[t];
        float4 k4 = ((const float4*)sk)[t];
        float4 q4 = ((const float4*)sq)[t];
        float4 n4;
        n4.x = fmaf(f4.x, p4.x, i4.x * k4.x);
        n4.y = fmaf(f4.y, p4.y, i4.y * k4.y);
        n4.z = fmaf(f4.z, p4.z, i4.z * k4.z);
        n4.w = fmaf(f4.w, p4.w, i4.w * k4.w);
        if (blockIdx.x == 0)
            ((float4*)(out_n + b * M_))[t] = n4;
        float part = n4.x * q4.x + n4.y * q4.y + n4.z * q4.z + n4.w * q4.w;
        #pragma unroll
        for (int off = 16; off; off >>= 1)
            part += __shfl_xor_sync(0xffffffffu, part, off);
        if (lane == 0) red[warp] = part;
        __syncthreads();
        if (threadIdx.x == 0) {
            float d = red[0] + red[1] + red[2] + red[3]
                    + red[4] + red[5] + red[6] + red[7];
            s_inv = 1.0f / fmaxf(d, 1.0f);
        }
        __syncthreads();
    }
    const float inv = s_inv;

    const float4* sk4 = (const float4*)sk;
    const float4* sq4 = (const float4*)sq;

    const int m_base = blockIdx.x * 64 + warp;

    float4 cur[8], nxt[8];
    int m = m_base;
    float fm = gf[m];
    float cm = gi[m] * gv[m];
    {
        const float4* cp = (const float4*)(Cprev + ((size_t)b * M_ + m) * M_);
        #pragma unroll
        for (int j = 0; j < 8; j++) cur[j] = __ldcs(cp + j * 32 + lane);
    }

    #pragma unroll
    for (int r = 0; r < 8; r++) {
        float fmn = 0.f, cmn = 0.f;
        if (r < 7) {
            const int mn = m_base + (r + 1) * 8;
            fmn = gf[mn];
            cmn = gi[mn] * gv[mn];
            const float4* cpn = (const float4*)(Cprev + ((size_t)b * M_ + mn) * M_);
            #pragma unroll
            for (int j = 0; j < 8; j++) nxt[j] = __ldcs(cpn + j * 32 + lane);
        }

        float4* co = (float4*)(Cout + ((size_t)b * M_ + m) * M_);
        float dot0 = 0.f, dot1 = 0.f;
        #pragma unroll
        for (int j = 0; j < 8; j++) {
            const int n4 = j * 32 + lane;
            float4 kk = sk4[n4];
            float4 qq = sq4[n4];
            float4 o;
            o.x = fmaf(fm, cur[j].x, cm * kk.x);
            o.y = fmaf(fm, cur[j].y, cm * kk.y);
            o.z = fmaf(fm, cur[j].z, cm * kk.z);
            o.w = fmaf(fm, cur[j].w, cm * kk.w);
            __stcs(co + n4, o);
            if (j & 1) {
                dot1 = fmaf(o.x, qq.x, dot1);
                dot1 = fmaf(o.y, qq.y, dot1);
                dot1 = fmaf(o.z, qq.z, dot1);
                dot1 = fmaf(o.w, qq.w, dot1);
            } else {
                dot0 = fmaf(o.x, qq.x, dot0);
                dot0 = fmaf(o.y, qq.y, dot0);
                dot0 = fmaf(o.z, qq.z, dot0);
                dot0 = fmaf(o.w, qq.w, dot0);
            }
        }
        float dot = dot0 + dot1;
        #pragma unroll
        for (int off = 16; off; off >>= 1)
            dot += __shfl_xor_sync(0xffffffffu, dot, off);
        if (lane == 0)
            out_h[b * M_ + m] = go[m] * dot * inv;

        m = m_base + (r + 1) * 8;
        fm = fmn;
        cm = cmn;
        #pragma unroll
        for (int j = 0; j < 8; j++) cur[j] = nxt[j];
    }
}

// ---------------------------------------------------------------------------
// Launch. Inputs (metadata order):
// 0 x, 1 h_prev, 2 c_prev, 3 C_prev, 4 n_prev, 5 m_prev,
// 6 Wq, 7 bq, 8 Wk, 9 bk, 10 Wv, 11 bv, 12 Wi, 13 bi, 14 Wf, 15 bf, 16 Wo, 17 bo
// Output: concat(h_t [64*1024], C_t [64*1024*1024], n_t [64*1024])
// ---------------------------------------------------------------------------
extern "C" void kernel_launch(void* const* d_in, const int* in_sizes, int n_in,
                              void* d_out, int out_size)
{
    const float* x     = (const float*)d_in[0];
    const float* Cprev = (const float*)d_in[3];
    const float* nprev = (const float*)d_in[4];

    const float* Wq = (const float*)d_in[6];  const float* bq = (const float*)d_in[7];
    const float* Wk = (const float*)d_in[8];  const float* bk = (const float*)d_in[9];
    const float* Wv = (const float*)d_in[10]; const float* bv = (const float*)d_in[11];
    const float* Wi = (const float*)d_in[12]; const float* bi = (const float*)d_in[13];
    const float* Wf = (const float*)d_in[14]; const float* bf = (const float*)d_in[15];
    const float* Wo = (const float*)d_in[16]; const float* bo = (const float*)d_in[17];

    float* out   = (float*)d_out;
    float* out_h = out;                                    // [64*1024]
    float* out_C = out + (size_t)B_ * M_;                  // [64*1024*1024]
    float* out_n = out + (size_t)B_ * M_ + (size_t)B_ * M_ * M_;

    dim3 grid1(96, NSPLIT);
    gates_mma_sk<<<grid1, 256>>>(x, Wq, Wk, Wv, Wi, Wf, Wo);

    gates_reduce<<<384, 256>>>(bq, bk, bv, bi, bf, bo);

    dim3 grid2(16, 64);
    update_C<<<grid2, 256>>>(Cprev, nprev, out_C, out_h, out_n);
}